// round 11
// baseline (speedup 1.0000x reference)
#include <cuda_runtime.h>
#include <cuda_bf16.h>
#include <cstdint>

#define F_OUT 2080
#define FP2   2176                // 17*128, 34*64
#define DD    1024
#define NB    16
#define KP    3072                // slots per plane (3 per original k)
#define ROWL  9216                // 3 planes * KP
#define BK    64
#define NIT   48                  // KP/BK
#define STGB  73728               // 3*16KB A-planes + 3*8KB B-planes
#define SMEM_BYTES (2 * STGB)     // 144KB, 1 CTA/SM

typedef __nv_bfloat16 bf16;

__device__ bf16 g_A1[(size_t)FP2 * ROWL];          // stage1 A (A-pattern)
__device__ bf16 g_A2[(size_t)FP2 * ROWL];          // stage2 B (B-pattern, conj)
__device__ bf16 g_B1[(size_t)NB * DD * ROWL];      // stage1 B (B-pattern)
__device__ bf16 g_T [(size_t)NB * FP2 * ROWL];     // intermediate (A-pattern)

// ---------------- helpers ----------------------------------------------------
__device__ __forceinline__ uint32_t s2u(const void* p) {
    uint32_t a; asm("{ .reg .u64 t; cvta.to.shared.u64 t, %1; cvt.u32.u64 %0, t; }"
                    : "=r"(a) : "l"(p)); return a;
}
__device__ __forceinline__ void cpa(uint32_t sa, const void* g) {
    asm volatile("cp.async.cg.shared.global [%0], [%1], 16;" :: "r"(sa), "l"(g));
}
#define CP_COMMIT() asm volatile("cp.async.commit_group;" ::: "memory")

__device__ __forceinline__ void ldsm4(uint32_t (&r)[4], uint32_t a) {
    asm volatile("ldmatrix.sync.aligned.m8n8.x4.shared.b16 {%0,%1,%2,%3}, [%4];"
        : "=r"(r[0]), "=r"(r[1]), "=r"(r[2]), "=r"(r[3]) : "r"(a));
}
__device__ __forceinline__ void mma16816(float (&d)[4], const uint32_t (&a)[4],
                                         uint32_t b0, uint32_t b1) {
    asm volatile("mma.sync.aligned.m16n8k16.row.col.f32.bf16.bf16.f32 "
        "{%0,%1,%2,%3},{%4,%5,%6,%7},{%8,%9},{%0,%1,%2,%3};"
        : "+f"(d[0]), "+f"(d[1]), "+f"(d[2]), "+f"(d[3])
        : "r"(a[0]), "r"(a[1]), "r"(a[2]), "r"(a[3]), "r"(b0), "r"(b1));
}
__device__ __forceinline__ void splt(float x, float& h, float& l) {
    h = __bfloat162float(__float2bfloat16_rn(x)); l = x - h;
}
__device__ __forceinline__ uint32_t pk2(float a, float b) {
    unsigned short ua = __bfloat16_as_ushort(__float2bfloat16_rn(a));
    unsigned short ub = __bfloat16_as_ushort(__float2bfloat16_rn(b));
    return (uint32_t)ua | ((uint32_t)ub << 16);
}
// A-pattern pair: k0 [h0,l0,h0], k1 [h1,l1,h1]
__device__ __forceinline__ void wrA(bf16* base, int k0, float h0, float l0,
                                    float h1, float l1) {
    uint32_t* p = (uint32_t*)(base + 3 * k0);
    p[0] = pk2(h0, l0); p[1] = pk2(h0, h1); p[2] = pk2(l1, h1);
}
// B-pattern pair: k0 [h0,h0,l0], k1 [h1,h1,l1]
__device__ __forceinline__ void wrB(bf16* base, int k0, float h0, float l0,
                                    float h1, float l1) {
    uint32_t* p = (uint32_t*)(base + 3 * k0);
    p[0] = pk2(h0, h0); p[1] = pk2(l0, h1); p[2] = pk2(h1, l1);
}

// ---------------- pack A (stage1 A-planes + stage2 B-planes) -----------------
__global__ void pack_amps(const float* __restrict__ U_re, const float* __restrict__ U_im) {
    int f = blockIdx.x, t = threadIdx.x;
    if (f >= F_OUT) {
        uint4 z = make_uint4(0, 0, 0, 0);
        uint4* a = (uint4*)(g_A1 + (size_t)f * ROWL);
        uint4* b = (uint4*)(g_A2 + (size_t)f * ROWL);
        for (int i = t; i < ROWL / 8; i += 256) { a[i] = z; b[i] = z; }
        return;
    }
    int j = 0, rem = f;
    while (rem >= 64 - j) { rem -= 64 - j; ++j; }
    int k = j + rem;
    __shared__ float su[4][64];
    if (t < 64) { su[0][t] = U_re[j*64+t]; su[1][t] = U_im[j*64+t];
                  su[2][t] = U_re[k*64+t]; su[3][t] = U_im[k*64+t]; }
    __syncthreads();
    float sc = (j == k) ? 0.7071067811865476f : 1.0f;
    bf16* A1 = g_A1 + (size_t)f * ROWL;
    bf16* A2 = g_A2 + (size_t)f * ROWL;
    for (int q = t; q < 512; q += 256) {
        float re[2], im[2];
#pragma unroll
        for (int e = 0; e < 2; ++e) {
            int i = 2 * q + e, x = i >> 5, y = i & 31;
            float ar = su[0][x], ai = su[1][x], br = su[2][32+y], bi = su[3][32+y];
            float cr = su[2][x], ci = su[3][x], dr = su[0][32+y], di = su[1][32+y];
            re[e] = sc * (ar*br - ai*bi + cr*dr - ci*di);
            im[e] = sc * (ar*bi + ai*br + cr*di + ci*dr);
        }
        float rh0,rl0,rh1,rl1, ih0,il0,ih1,il1, sh0,sl0,sh1,sl1, dh0,dl0,dh1,dl1;
        splt(re[0],rh0,rl0); splt(re[1],rh1,rl1);
        splt(im[0],ih0,il0); splt(im[1],ih1,il1);
        splt(re[0]+im[0],sh0,sl0); splt(re[1]+im[1],sh1,sl1);
        splt(re[0]-im[0],dh0,dl0); splt(re[1]-im[1],dh1,dl1);
        int k0 = 2 * q;
        wrA(A1,          k0, rh0, rl0, rh1, rl1);     // P0: Ar
        wrA(A1 + KP,     k0, ih0, il0, ih1, il1);     // P1: Ai
        wrA(A1 + 2*KP,   k0, sh0, sl0, sh1, sl1);     // P2: Ar+Ai
        wrB(A2,          k0, rh0, rl0, rh1, rl1);     // B'r = Ar
        wrB(A2 + KP,     k0, -ih0, -il0, -ih1, -il1); // B'i = -Ai
        wrB(A2 + 2*KP,   k0, dh0, dl0, dh1, dl1);     // B'r+B'i = Ar-Ai
    }
}

// ---------------- pack B (stage1 B-planes from rho upper triangle) -----------
__global__ void pack_B(const float* __restrict__ rr, const float* __restrict__ ri) {
    int n = blockIdx.x, b = blockIdx.y, t = threadIdx.x;
    const size_t rb = (size_t)b * DD * DD;
    bf16* B1 = g_B1 + ((size_t)b * DD + n) * ROWL;
    for (int q = t; q < 512; q += 256) {
        float Br[2], Bi[2];
#pragma unroll
        for (int e = 0; e < 2; ++e) {
            int k = 2 * q + e;
            if (k < n)      { Br[e] = rr[rb + (size_t)k*DD + n]; Bi[e] = ri[rb + (size_t)k*DD + n]; }
            else if (k > n) { Br[e] = rr[rb + (size_t)n*DD + k]; Bi[e] = -ri[rb + (size_t)n*DD + k]; }
            else            { Br[e] = rr[rb + (size_t)n*DD + n]; Bi[e] = 0.f; }
        }
        float rh0,rl0,rh1,rl1, ih0,il0,ih1,il1, sh0,sl0,sh1,sl1;
        splt(Br[0],rh0,rl0); splt(Br[1],rh1,rl1);
        splt(Bi[0],ih0,il0); splt(Bi[1],ih1,il1);
        splt(Br[0]+Bi[0],sh0,sl0); splt(Br[1]+Bi[1],sh1,sl1);
        int k0 = 2 * q;
        wrB(B1,        k0, rh0, rl0, rh1, rl1);   // P0: Hr
        wrB(B1 + KP,   k0, ih0, il0, ih1, il1);   // P1: Hi
        wrB(B1 + 2*KP, k0, sh0, sl0, sh1, sl1);   // P2: Hr+Hi
    }
}

// ---------------- 3-plane Karatsuba warp-MMA GEMM ----------------------------
// CTA: M=128 x N=64 complex. 384 threads = 12 warps = plane(3) x mh(2) x nh(2),
// warp tile 64x32 real. 2-stage cp.async pipeline + frag double-buffering.
template <int STAGE>
__global__ void __launch_bounds__(384, 1) gemm_mma(float* __restrict__ out) {
    const int tid = threadIdx.x, lane = tid & 31, wid = tid >> 5;
    const int bx = blockIdx.x, by = blockIdx.y, bz = blockIdx.z;
    if (STAGE == 2 && 64 * (bx + 1) <= 128 * by) return;
    extern __shared__ __align__(128) char smem[];
    const uint32_t sb = s2u(smem);

    const bf16 *Ag, *Bg;
    if (STAGE == 1) {
        Ag = g_A1 + (size_t)(by * 128) * ROWL;
        Bg = g_B1 + ((size_t)bz * DD + bx * 64) * ROWL;
    } else {
        Ag = g_T  + ((size_t)bz * FP2 + by * 128) * ROWL;
        Bg = g_A2 + (size_t)(bx * 64) * ROWL;
    }
    const int plane = wid >> 2, mh = (wid >> 1) & 1, nh = wid & 1;

    float acc[4][4][4];
#pragma unroll
    for (int a = 0; a < 4; ++a)
#pragma unroll
        for (int b2 = 0; b2 < 4; ++b2)
#pragma unroll
            for (int c2 = 0; c2 < 4; ++c2) acc[a][b2][c2] = 0.f;

    // loader indices
    const int apl = tid >> 7, arow = tid & 127;            // A: plane, row (8 lines)
    const int bsel = tid >> 6, brow = tid & 63;            // B: sel(0..5), row (4 lines)
    const int bpl = bsel >> 1, bhalf = bsel & 1;

    auto load_stage = [&](int c, int buf) {
        uint32_t bb = sb + buf * STGB;
        const bf16* as = Ag + (size_t)arow * ROWL + apl * KP + c * BK;
        uint32_t adst = bb + apl * 16384 + arow * 128;
#pragma unroll
        for (int i = 0; i < 8; ++i)
            cpa(adst + ((i ^ (arow & 7)) << 4), as + i * 8);
        const bf16* bs = Bg + (size_t)brow * ROWL + bpl * KP + c * BK + bhalf * 32;
        uint32_t bdst = bb + 49152 + bpl * 8192 + brow * 128;
#pragma unroll
        for (int i = 0; i < 4; ++i) {
            int ch = bhalf * 4 + i;
            cpa(bdst + ((ch ^ (brow & 7)) << 4), bs + i * 8);
        }
    };

    load_stage(0, 0); CP_COMMIT();

    uint32_t af[2][4][4], bfr[2][2][4];
    for (int c = 0; c < NIT; ++c) {
        asm volatile("cp.async.wait_group 0;" ::: "memory");
        __syncthreads();
        if (c + 1 < NIT) { load_stage(c + 1, (c + 1) & 1); CP_COMMIT(); }

        const uint32_t bb = sb + (c & 1) * STGB;
        const uint32_t sA = bb + plane * 16384;
        const uint32_t sB = bb + 49152 + plane * 8192;

#pragma unroll
        for (int mi = 0; mi < 4; ++mi) {
            int m = mh * 64 + mi * 16 + (lane & 15);
            int ch = (lane >> 4);
            ldsm4(af[0][mi], sA + m * 128 + ((ch ^ (m & 7)) << 4));
        }
#pragma unroll
        for (int nj = 0; nj < 2; ++nj) {
            int n = nh * 32 + nj * 16 + (lane & 7) + ((lane >> 4) << 3);
            int ch = ((lane >> 3) & 1);
            ldsm4(bfr[0][nj], sB + n * 128 + ((ch ^ (n & 7)) << 4));
        }
#pragma unroll
        for (int ks = 0; ks < 4; ++ks) {
            const int cur = ks & 1, nxt = cur ^ 1;
            if (ks < 3) {
#pragma unroll
                for (int mi = 0; mi < 4; ++mi) {
                    int m = mh * 64 + mi * 16 + (lane & 15);
                    int ch = (ks + 1) * 2 + (lane >> 4);
                    ldsm4(af[nxt][mi], sA + m * 128 + ((ch ^ (m & 7)) << 4));
                }
#pragma unroll
                for (int nj = 0; nj < 2; ++nj) {
                    int n = nh * 32 + nj * 16 + (lane & 7) + ((lane >> 4) << 3);
                    int ch = (ks + 1) * 2 + ((lane >> 3) & 1);
                    ldsm4(bfr[nxt][nj], sB + n * 128 + ((ch ^ (n & 7)) << 4));
                }
            }
#pragma unroll
            for (int mi = 0; mi < 4; ++mi)
#pragma unroll
                for (int ni = 0; ni < 4; ++ni)
                    mma16816(acc[mi][ni], af[cur][mi],
                             bfr[cur][ni >> 1][(ni & 1) * 2],
                             bfr[cur][ni >> 1][(ni & 1) * 2 + 1]);
        }
    }

    // ---- epilogue: stage 3 plane accumulators, combine, write ----------------
    __syncthreads();
    float* st = (float*)smem + plane * 8192;      // 32KB per plane
#pragma unroll
    for (int mi = 0; mi < 4; ++mi)
#pragma unroll
        for (int ni = 0; ni < 4; ++ni) {
            int r0 = mh * 64 + mi * 16 + (lane >> 2);
            int col = nh * 32 + ni * 8 + (lane & 3) * 2;
            *(float2*)&st[r0 * 64 + col]       = make_float2(acc[mi][ni][0], acc[mi][ni][1]);
            *(float2*)&st[(r0 + 8) * 64 + col] = make_float2(acc[mi][ni][2], acc[mi][ni][3]);
        }
    __syncthreads();

    if (tid < 256) {
        const int row = tid >> 1, c0 = (tid & 1) * 32;
        const float* p0 = (float*)smem + row * 64 + c0;
        const float* p1 = p0 + 8192;
        const float* p2 = p1 + 8192;
        const int f = by * 128 + row;
        if (STAGE == 1) {
            bf16* Trow = g_T + ((size_t)bz * FP2 + f) * ROWL;
#pragma unroll 4
            for (int m = 0; m < 16; ++m) {
                float re0 = p0[2*m]   - p1[2*m],   im0 = p2[2*m]   - p0[2*m]   - p1[2*m];
                float re1 = p0[2*m+1] - p1[2*m+1], im1 = p2[2*m+1] - p0[2*m+1] - p1[2*m+1];
                float rh0,rl0,rh1,rl1, ih0,il0,ih1,il1, sh0,sl0,sh1,sl1;
                splt(re0,rh0,rl0); splt(re1,rh1,rl1);
                splt(im0,ih0,il0); splt(im1,ih1,il1);
                splt(re0+im0,sh0,sl0); splt(re1+im1,sh1,sl1);
                int n0 = bx * 64 + c0 + 2 * m;
                wrA(Trow,          n0, rh0, rl0, rh1, rl1);
                wrA(Trow + KP,     n0, ih0, il0, ih1, il1);
                wrA(Trow + 2*KP,   n0, sh0, sl0, sh1, sl1);
            }
        } else {
            if (f < F_OUT) {
                float2* o = (float2*)out + (size_t)bz * F_OUT * F_OUT;
#pragma unroll 4
                for (int j2 = 0; j2 < 32; ++j2) {
                    int g = bx * 64 + c0 + j2;
                    if (g < F_OUT && f <= g) {
                        float re = p0[j2] - p1[j2];
                        float im = p2[j2] - p0[j2] - p1[j2];
                        if (f == g) im = 0.f;
                        o[(size_t)f * F_OUT + g] = make_float2(re, im);
                        if (f < g) o[(size_t)g * F_OUT + f] = make_float2(re, -im);
                    }
                }
            }
        }
    }
}

// ---------------- launch -----------------------------------------------------
extern "C" void kernel_launch(void* const* d_in, const int* in_sizes, int n_in,
                              void* d_out, int out_size) {
    const float* rho_re = (const float*)d_in[0];
    const float* rho_im = (const float*)d_in[1];
    const float* U_re   = (const float*)d_in[2];
    const float* U_im   = (const float*)d_in[3];

    cudaFuncSetAttribute(gemm_mma<1>, cudaFuncAttributeMaxDynamicSharedMemorySize, SMEM_BYTES);
    cudaFuncSetAttribute(gemm_mma<2>, cudaFuncAttributeMaxDynamicSharedMemorySize, SMEM_BYTES);

    pack_amps<<<FP2, 256>>>(U_re, U_im);
    pack_B<<<dim3(DD, NB), 256>>>(rho_re, rho_im);
    gemm_mma<1><<<dim3(16, 17, NB), 384, SMEM_BYTES>>>(nullptr);
    gemm_mma<2><<<dim3(34, 17, NB), 384, SMEM_BYTES>>>((float*)d_out);
}

// round 12
// speedup vs baseline: 1.9255x; 1.9255x over previous
#include <cuda_runtime.h>
#include <cuda_bf16.h>
#include <cstdint>

#define F_OUT 2080
#define FP2   2176                // 17*128
#define DD    1024
#define NB    16
#define KEFF  6144                // 6 bf16 slots per original k
#define BK    64
#define NIT   96                  // KEFF/BK
#define STGB  49152               // per stage: A 16KB + Bre 16KB + Bim 16KB
#define SMEM_BYTES (3 * STGB)     // 144KB, 1 CTA/SM (512 threads)

typedef __nv_bfloat16 bf16;

__device__ bf16 g_Apk [(size_t)FP2 * KEFF];
__device__ bf16 g_A2re[(size_t)FP2 * KEFF];
__device__ bf16 g_A2im[(size_t)FP2 * KEFF];
__device__ bf16 g_Bre [(size_t)NB * DD * KEFF];
__device__ bf16 g_Bim [(size_t)NB * DD * KEFF];
__device__ bf16 g_Tpk [(size_t)NB * FP2 * KEFF];

// ---------------- helpers ----------------------------------------------------
__device__ __forceinline__ uint32_t s2u(const void* p) {
    uint32_t a; asm("{ .reg .u64 t; cvta.to.shared.u64 t, %1; cvt.u32.u64 %0, t; }"
                    : "=r"(a) : "l"(p)); return a;
}
__device__ __forceinline__ void cpa(uint32_t sa, const void* g) {
    asm volatile("cp.async.cg.shared.global [%0], [%1], 16;" :: "r"(sa), "l"(g));
}
#define CP_COMMIT() asm volatile("cp.async.commit_group;" ::: "memory")

__device__ __forceinline__ void ldsm4(uint32_t (&r)[4], uint32_t a) {
    asm volatile("ldmatrix.sync.aligned.m8n8.x4.shared.b16 {%0,%1,%2,%3}, [%4];"
        : "=r"(r[0]), "=r"(r[1]), "=r"(r[2]), "=r"(r[3]) : "r"(a));
}
__device__ __forceinline__ void mma16816(float (&d)[4], const uint32_t (&a)[4],
                                         uint32_t b0, uint32_t b1) {
    asm volatile("mma.sync.aligned.m16n8k16.row.col.f32.bf16.bf16.f32 "
        "{%0,%1,%2,%3},{%4,%5,%6,%7},{%8,%9},{%0,%1,%2,%3};"
        : "+f"(d[0]), "+f"(d[1]), "+f"(d[2]), "+f"(d[3])
        : "r"(a[0]), "r"(a[1]), "r"(a[2]), "r"(a[3]), "r"(b0), "r"(b1));
}
__device__ __forceinline__ void splt(float x, float& h, float& l) {
    h = __bfloat162float(__float2bfloat16_rn(x)); l = x - h;
}
__device__ __forceinline__ uint32_t pk2(float a, float b) {
    unsigned short ua = __bfloat16_as_ushort(__float2bfloat16_rn(a));
    unsigned short ub = __bfloat16_as_ushort(__float2bfloat16_rn(b));
    return (uint32_t)ua | ((uint32_t)ub << 16);
}

// ---------------- pack A (stage1 A-plane + stage2 B-planes) ------------------
__global__ void pack_amps(const float* __restrict__ U_re, const float* __restrict__ U_im) {
    int f = blockIdx.x, t = threadIdx.x;
    if (f >= F_OUT) {
        uint4 z = make_uint4(0, 0, 0, 0);
        uint4* a = (uint4*)(g_Apk  + (size_t)f * KEFF);
        uint4* r = (uint4*)(g_A2re + (size_t)f * KEFF);
        uint4* m = (uint4*)(g_A2im + (size_t)f * KEFF);
        for (int i = t; i < KEFF / 8; i += 256) { a[i] = z; r[i] = z; m[i] = z; }
        return;
    }
    int j = 0, rem = f;
    while (rem >= 64 - j) { rem -= 64 - j; ++j; }
    int k = j + rem;
    __shared__ float su[4][64];
    if (t < 64) { su[0][t] = U_re[j*64+t]; su[1][t] = U_im[j*64+t];
                  su[2][t] = U_re[k*64+t]; su[3][t] = U_im[k*64+t]; }
    __syncthreads();
    float sc = (j == k) ? 0.7071067811865476f : 1.0f;
    for (int i = t; i < DD; i += 256) {
        int x = i >> 5, y = i & 31;
        float ar = su[0][x], ai = su[1][x], br = su[2][32+y], bi = su[3][32+y];
        float cr = su[2][x], ci = su[3][x], dr = su[0][32+y], di = su[1][32+y];
        float re = sc * (ar*br - ai*bi + cr*dr - ci*di);
        float im = sc * (ar*bi + ai*br + cr*di + ci*dr);
        float rh, rl, ih, il; splt(re, rh, rl); splt(im, ih, il);
        size_t e = (size_t)f * KEFF + 6 * i;
        uint32_t* pA = (uint32_t*)(g_Apk  + e);
        uint32_t* pR = (uint32_t*)(g_A2re + e);
        uint32_t* pI = (uint32_t*)(g_A2im + e);
        pA[0]=pk2(rh,rl);   pA[1]=pk2(rh,ih);  pA[2]=pk2(il,ih);
        pR[0]=pk2(rh,rh);   pR[1]=pk2(rl,ih);  pR[2]=pk2(ih,il);
        pI[0]=pk2(-ih,-ih); pI[1]=pk2(-il,rh); pI[2]=pk2(rh,rl);
    }
}

// ---------------- pack B (stage1 B-planes from rho upper triangle) -----------
__global__ void pack_B(const float* __restrict__ rr, const float* __restrict__ ri) {
    int n = blockIdx.x, b = blockIdx.y, t = threadIdx.x;
    const size_t rb = (size_t)b * DD * DD;
    for (int k = t; k < DD; k += 256) {
        float Br, Bi;
        if (k < n)      { Br = rr[rb + (size_t)k*DD + n]; Bi = ri[rb + (size_t)k*DD + n]; }
        else if (k > n) { Br = rr[rb + (size_t)n*DD + k]; Bi = -ri[rb + (size_t)n*DD + k]; }
        else            { Br = rr[rb + (size_t)n*DD + n]; Bi = 0.f; }
        float rh, rl, ih, il; splt(Br, rh, rl); splt(Bi, ih, il);
        size_t e = ((size_t)b*DD + n) * KEFF + 6*k;
        uint32_t* pR = (uint32_t*)(g_Bre + e);
        uint32_t* pI = (uint32_t*)(g_Bim + e);
        pR[0]=pk2(rh,rh); pR[1]=pk2(rl,-ih); pR[2]=pk2(-ih,-il);
        pI[0]=pk2(ih,ih); pI[1]=pk2(il,rh);  pI[2]=pk2(rh,rl);
    }
}

// ---------------- warp-MMA GEMM (both stages) --------------------------------
// CTA: M=128 x N=128 complex, 512 threads = 16 warps = plane(2) x mh(2) x nh(4),
// warp tile 64x32 real. 3-stage cp.async pipeline + frag double-buffering.
template <int STAGE>
__global__ void __launch_bounds__(512, 1) gemm_mma(float* __restrict__ out) {
    const int tid = threadIdx.x, lane = tid & 31, wid = tid >> 5;
    const int bx = blockIdx.x, by = blockIdx.y, bz = blockIdx.z;
    if (STAGE == 2 && bx < by) return;       // Hermitian: tile fully below diag
    extern __shared__ __align__(128) char smem[];
    const uint32_t sb = s2u(smem);

    const bf16 *Ag, *Brg, *Big;
    if (STAGE == 1) {
        Ag  = g_Apk + (size_t)(by * 128) * KEFF;
        Brg = g_Bre + ((size_t)bz * DD + bx * 128) * KEFF;
        Big = g_Bim + ((size_t)bz * DD + bx * 128) * KEFF;
    } else {
        Ag  = g_Tpk + ((size_t)bz * FP2 + by * 128) * KEFF;
        Brg = g_A2re + (size_t)(bx * 128) * KEFF;
        Big = g_A2im + (size_t)(bx * 128) * KEFF;
    }
    const int plane = wid & 1, mh = (wid >> 1) & 1, nh = wid >> 2;   // nh: 0..3

    float acc[4][4][4];
#pragma unroll
    for (int a = 0; a < 4; ++a)
#pragma unroll
        for (int b2 = 0; b2 < 4; ++b2)
#pragma unroll
            for (int c2 = 0; c2 < 4; ++c2) acc[a][b2][c2] = 0.f;

    // loader: r = row (0..127), q*2 lines of 16B; 6 cp.async per thread/stage
    const int lr = tid >> 2, lq = (tid & 3) * 2;

    auto load_stage = [&](int c, int buf) {
        uint32_t bb = sb + buf * STGB;
        const bf16* as = Ag  + (size_t)lr * KEFF + c * BK;
        const bf16* rs = Brg + (size_t)lr * KEFF + c * BK;
        const bf16* is = Big + (size_t)lr * KEFF + c * BK;
#pragma unroll
        for (int i = 0; i < 2; ++i) {
            int ch = lq + i;
            uint32_t sw = lr * 128 + ((ch ^ (lr & 7)) << 4);
            cpa(bb + sw,         as + ch * 8);
            cpa(bb + 16384 + sw, rs + ch * 8);
            cpa(bb + 32768 + sw, is + ch * 8);
        }
    };

    load_stage(0, 0); CP_COMMIT();
    load_stage(1, 1); CP_COMMIT();

    uint32_t af[2][4][4], bfr[2][2][4];

    int buf = 0;
    for (int c = 0; c < NIT; ++c) {
        if (c + 1 < NIT) asm volatile("cp.async.wait_group 1;" ::: "memory");
        else             asm volatile("cp.async.wait_group 0;" ::: "memory");
        __syncthreads();
        if (c + 2 < NIT) {
            int nb = buf + 2; if (nb >= 3) nb -= 3;
            load_stage(c + 2, nb);
            CP_COMMIT();
        }
        const uint32_t bb = sb + buf * STGB;
        const uint32_t sA = bb;
        const uint32_t sB = bb + 16384 + plane * 16384;

        // prefetch ks=0 fragments
#pragma unroll
        for (int mi = 0; mi < 4; ++mi) {
            int m = mh * 64 + mi * 16 + (lane & 15);
            int ch = (lane >> 4);
            ldsm4(af[0][mi], sA + m * 128 + ((ch ^ (m & 7)) << 4));
        }
#pragma unroll
        for (int nj = 0; nj < 2; ++nj) {
            int n = nh * 32 + nj * 16 + (lane & 7) + ((lane >> 4) << 3);
            int ch = ((lane >> 3) & 1);
            ldsm4(bfr[0][nj], sB + n * 128 + ((ch ^ (n & 7)) << 4));
        }
#pragma unroll
        for (int ks = 0; ks < 4; ++ks) {
            const int cur = ks & 1, nxt = cur ^ 1;
            if (ks < 3) {
#pragma unroll
                for (int mi = 0; mi < 4; ++mi) {
                    int m = mh * 64 + mi * 16 + (lane & 15);
                    int ch = (ks + 1) * 2 + (lane >> 4);
                    ldsm4(af[nxt][mi], sA + m * 128 + ((ch ^ (m & 7)) << 4));
                }
#pragma unroll
                for (int nj = 0; nj < 2; ++nj) {
                    int n = nh * 32 + nj * 16 + (lane & 7) + ((lane >> 4) << 3);
                    int ch = (ks + 1) * 2 + ((lane >> 3) & 1);
                    ldsm4(bfr[nxt][nj], sB + n * 128 + ((ch ^ (n & 7)) << 4));
                }
            }
#pragma unroll
            for (int mi = 0; mi < 4; ++mi)
#pragma unroll
                for (int ni = 0; ni < 4; ++ni)
                    mma16816(acc[mi][ni], af[cur][mi],
                             bfr[cur][ni >> 1][(ni & 1) * 2],
                             bfr[cur][ni >> 1][(ni & 1) * 2 + 1]);
        }
        if (++buf == 3) buf = 0;
    }

    // ---- epilogue: stage planes in smem (re @0, im @64KB), combine, write ----
    __syncthreads();
    float* stR = (float*)smem;
    float* stI = (float*)(smem + 65536);
    float* st = plane ? stI : stR;
#pragma unroll
    for (int mi = 0; mi < 4; ++mi)
#pragma unroll
        for (int ni = 0; ni < 4; ++ni) {
            int r0 = mh * 64 + mi * 16 + (lane >> 2);
            int col = nh * 32 + ni * 8 + (lane & 3) * 2;
            *(float2*)&st[r0 * 128 + col]       = make_float2(acc[mi][ni][0], acc[mi][ni][1]);
            *(float2*)&st[(r0 + 8) * 128 + col] = make_float2(acc[mi][ni][2], acc[mi][ni][3]);
        }
    __syncthreads();

    const int row = tid >> 2;
    const int c0 = (tid & 3) * 32;
    if (STAGE == 1) {
        int f = by * 128 + row;
        char* Trow = (char*)(g_Tpk + ((size_t)bz * FP2 + f) * KEFF);
#pragma unroll 2
        for (int m = 0; m < 8; ++m) {
            uint32_t u[12];
#pragma unroll
            for (int t2 = 0; t2 < 4; ++t2) {
                float re = stR[row * 128 + c0 + m * 4 + t2];
                float im = stI[row * 128 + c0 + m * 4 + t2];
                float rh, rl, ih, il; splt(re, rh, rl); splt(im, ih, il);
                u[t2*3+0] = pk2(rh, rl); u[t2*3+1] = pk2(rh, ih); u[t2*3+2] = pk2(il, ih);
            }
            int n0 = bx * 128 + c0 + m * 4;
            uint4* p = (uint4*)(Trow + (size_t)12 * n0);
            p[0] = make_uint4(u[0], u[1], u[2],  u[3]);
            p[1] = make_uint4(u[4], u[5], u[6],  u[7]);
            p[2] = make_uint4(u[8], u[9], u[10], u[11]);
        }
    } else {
        int f = by * 128 + row;
        if (f < F_OUT) {
            float2* o = (float2*)out + (size_t)bz * F_OUT * F_OUT;
#pragma unroll 4
            for (int j2 = 0; j2 < 32; ++j2) {
                int g = bx * 128 + c0 + j2;
                if (g < F_OUT && f <= g) {
                    float re = stR[row * 128 + c0 + j2];
                    float im = stI[row * 128 + c0 + j2];
                    if (f == g) im = 0.f;
                    o[(size_t)f * F_OUT + g] = make_float2(re, im);
                    if (f < g) o[(size_t)g * F_OUT + f] = make_float2(re, -im);
                }
            }
        }
    }
}

// ---------------- launch -----------------------------------------------------
extern "C" void kernel_launch(void* const* d_in, const int* in_sizes, int n_in,
                              void* d_out, int out_size) {
    const float* rho_re = (const float*)d_in[0];
    const float* rho_im = (const float*)d_in[1];
    const float* U_re   = (const float*)d_in[2];
    const float* U_im   = (const float*)d_in[3];

    cudaFuncSetAttribute(gemm_mma<1>, cudaFuncAttributeMaxDynamicSharedMemorySize, SMEM_BYTES);
    cudaFuncSetAttribute(gemm_mma<2>, cudaFuncAttributeMaxDynamicSharedMemorySize, SMEM_BYTES);

    pack_amps<<<FP2, 256>>>(U_re, U_im);
    pack_B<<<dim3(DD, NB), 256>>>(rho_re, rho_im);
    gemm_mma<1><<<dim3(8, 17, NB), 512, SMEM_BYTES>>>(nullptr);
    gemm_mma<2><<<dim3(17, 17, NB), 512, SMEM_BYTES>>>((float*)d_out);
}